// round 5
// baseline (speedup 1.0000x reference)
#include <cuda_runtime.h>
#include <cuda_fp16.h>
#include <cstddef>

// ---------------- problem constants ----------------
#define T_STEPS 100
#define BB 16
#define EE 128
#define HH 256
#define LL 2048
// output layout (flattened tuple: outputs, h_f, c_f, attn, p_gens)
#define OUT_OFF  0                    // [100,16,256] = 409600
#define HF_OFF   409600               // [16,256]
#define CF_OFF   413696               // [16,256]
#define ATTN_OFF 417792               // [100,16,2048] = 3276800
#define PG_OFF   3694592              // [100,16,1]

// ---------------- device scratch ----------------
__device__ float   g_enc_feat[BB * LL * HH];          // 33.5 MB fp32 (precision-critical path)
__device__ __half2 g_enc16[BB * LL * HH];             // 33.5 MB fp16 copy of encoder_states (512 cols = 256 half2)
__device__ float g_X [T_STEPS * BB * EE];             // x for all steps
__device__ float g_Xg[(T_STEPS * BB + 16) * 4 * HH];  // x@Wih^T+bih+bhh (padded 16 rows, zero-init)
__device__ float g_px[T_STEPS * BB];                  // x-part of p_gen + bpg
__device__ float g_h[2 * BB * HH];                    // double-buffered by step parity
__device__ float g_c[2 * BB * HH];
__device__ float g_dec[BB * HH];
__device__ float g_e[BB * LL];
__device__ float g_ctx[2 * BB * 2 * HH];              // double-buffered
__device__ float g_WhhT[HH * 4 * HH];                 // [256][1024]  (k-major)
__device__ float g_WsT [2 * HH * HH];                 // [512][256]
__device__ float g_WoutT[3 * HH * HH];                // [768][256]
__device__ float g_WihT[EE * 4 * HH];                 // [128][1024]

// ---------------- helpers ----------------
__device__ __forceinline__ float sigf(float x) {
    return __fdividef(1.f, 1.f + __expf(-x));
}
__device__ __forceinline__ float tanh_fast(float x) {
    float ax = fabsf(x);
    float t = __expf(-2.f * ax);
    float r = (1.f - t) * __fdividef(1.f, 1.f + t);
    return copysignf(r, x);
}

// ---------------- precompute kernels ----------------
__global__ void k_init(const float* __restrict__ h0, const float* __restrict__ c0) {
    int i = blockIdx.x * 256 + threadIdx.x;   // 16*256 = 4096
    g_h[i] = h0[i];
    g_c[i] = c0[i];
}

__global__ void k_enc16(const float* __restrict__ es) {
    int i = blockIdx.x * 256 + threadIdx.x;   // over 8388608 float-pairs
    float2 f = ((const float2*)es)[i];
    g_enc16[i] = __floats2half2_rn(f.x, f.y);
}

__global__ void k_transpose(const float* __restrict__ Whh, const float* __restrict__ Ws,
                            const float* __restrict__ Wout, const float* __restrict__ Wih) {
    int stride = gridDim.x * blockDim.x;
    int tid = blockIdx.x * blockDim.x + threadIdx.x;
    for (int i = tid; i < 1024 * 256; i += stride) {      // Whh [1024,256] -> [256,1024]
        int j = i / 256, k = i % 256;
        g_WhhT[k * 1024 + j] = Whh[i];
    }
    for (int i = tid; i < 256 * 512; i += stride) {       // Ws [256,512] -> [512,256]
        int j = i / 512, k = i % 512;
        g_WsT[k * 256 + j] = Ws[i];
    }
    for (int i = tid; i < 256 * 768; i += stride) {       // Wout [256,768] -> [768,256]
        int j = i / 768, k = i % 768;
        g_WoutT[k * 256 + j] = Wout[i];
    }
    for (int i = tid; i < 1024 * 128; i += stride) {      // Wih [1024,128] -> [128,1024]
        int j = i / 128, k = i % 128;
        g_WihT[k * 1024 + j] = Wih[i];
    }
}

// enc_feat = encoder_states(32768x512) @ Wh^T(512x256) + bh ; 64x64 tile, 4x4/thread
__global__ void k_encfeat(const float* __restrict__ A, const float* __restrict__ Wh,
                          const float* __restrict__ bh) {
    __shared__ __align__(16) float As[16 * 64];
    __shared__ __align__(16) float Bs[16 * 64];
    int m0 = blockIdx.x * 64, n0 = blockIdx.y * 64;
    int tid = threadIdx.x;
    int r = tid >> 2, c4 = (tid & 3) << 2;
    int rm = (tid & 15) << 2, rn = (tid >> 4) << 2;
    float acc[4][4] = {};
    for (int k0 = 0; k0 < 512; k0 += 16) {
        float4 av = *(const float4*)(A + (size_t)(m0 + r) * 512 + k0 + c4);
        As[(c4 + 0) * 64 + r] = av.x; As[(c4 + 1) * 64 + r] = av.y;
        As[(c4 + 2) * 64 + r] = av.z; As[(c4 + 3) * 64 + r] = av.w;
        float4 bv = *(const float4*)(Wh + (size_t)(n0 + r) * 512 + k0 + c4);
        Bs[(c4 + 0) * 64 + r] = bv.x; Bs[(c4 + 1) * 64 + r] = bv.y;
        Bs[(c4 + 2) * 64 + r] = bv.z; Bs[(c4 + 3) * 64 + r] = bv.w;
        __syncthreads();
#pragma unroll
        for (int kk = 0; kk < 16; kk++) {
            float4 a  = *(const float4*)(As + kk * 64 + rm);
            float4 bb = *(const float4*)(Bs + kk * 64 + rn);
            acc[0][0] += a.x * bb.x; acc[0][1] += a.x * bb.y; acc[0][2] += a.x * bb.z; acc[0][3] += a.x * bb.w;
            acc[1][0] += a.y * bb.x; acc[1][1] += a.y * bb.y; acc[1][2] += a.y * bb.z; acc[1][3] += a.y * bb.w;
            acc[2][0] += a.z * bb.x; acc[2][1] += a.z * bb.y; acc[2][2] += a.z * bb.z; acc[2][3] += a.z * bb.w;
            acc[3][0] += a.w * bb.x; acc[3][1] += a.w * bb.y; acc[3][2] += a.w * bb.z; acc[3][3] += a.w * bb.w;
        }
        __syncthreads();
    }
#pragma unroll
    for (int i = 0; i < 4; i++)
#pragma unroll
        for (int j = 0; j < 4; j++)
            g_enc_feat[(size_t)(m0 + rm + i) * 256 + n0 + rn + j] = acc[i][j] + bh[n0 + rn + j];
}

// X[m,:] = inp[m,:128] @ WxE^T + bx  (zero-context columns of Wx drop out)
__global__ void k_X(const float* __restrict__ inp, const float* __restrict__ Wx,
                    const float* __restrict__ bx) {
    int m = blockIdx.x, tid = threadIdx.x;   // 128 threads
    __shared__ float s_in[128];
    s_in[tid] = inp[m * 128 + tid];
    __syncthreads();
    const float* w = Wx + (size_t)tid * 640;
    float a0 = 0, a1 = 0, a2 = 0, a3 = 0;
#pragma unroll 8
    for (int k = 0; k < 128; k += 4) {
        a0 += s_in[k] * w[k]; a1 += s_in[k + 1] * w[k + 1];
        a2 += s_in[k + 2] * w[k + 2]; a3 += s_in[k + 3] * w[k + 3];
    }
    g_X[m * 128 + tid] = bx[tid] + (a0 + a1) + (a2 + a3);
}

// Xg[m,:] = X[m,:] @ Wih^T + bih + bhh ; 8 rows per block for weight reuse
__global__ void k_Xg(const float* __restrict__ bih, const float* __restrict__ bhh) {
    int m0 = blockIdx.x * 8;   // 200 blocks
    int tid = threadIdx.x;     // 256
    __shared__ float sx[8 * 128];
#pragma unroll
    for (int i = 0; i < 4; i++) sx[tid + i * 256] = g_X[m0 * 128 + tid + i * 256];
    __syncthreads();
#pragma unroll
    for (int g = 0; g < 4; g++) {
        int row = g * 256 + tid;
        float base = bih[row] + bhh[row];
        float acc[8];
#pragma unroll
        for (int mm = 0; mm < 8; mm++) acc[mm] = base;
        for (int k = 0; k < 128; k++) {
            float w = g_WihT[k * 1024 + row];
#pragma unroll
            for (int mm = 0; mm < 8; mm++) acc[mm] += sx[mm * 128 + k] * w;
        }
#pragma unroll
        for (int mm = 0; mm < 8; mm++) g_Xg[(m0 + mm) * 1024 + row] = acc[mm];
    }
}

// px[m] = X[m,:] . Wpg[1024:1152] + bpg
__global__ void k_px(const float* __restrict__ Wpg, const float* __restrict__ bpg) {
    int m = blockIdx.x * 128 + threadIdx.x;
    if (m >= T_STEPS * BB) return;
    const float* x = g_X + m * 128;
    float a0 = 0, a1 = 0;
#pragma unroll 8
    for (int k = 0; k < 128; k += 2) {
        a0 += x[k] * Wpg[1024 + k];
        a1 += x[k + 1] * Wpg[1024 + k + 1];
    }
    g_px[m] = a0 + a1 + bpg[0];
}

// ---------------- per-step kernels (weight-stationary across batch) ----------------
// k_step(t): [t>0] out(t-1) + p_gen(t-1), then gates+LSTM for step t, zero ctx parity t.
// grid 64 blocks (p = 4-wide j slice) x 256 threads. Operand reuse across the 16
// batch rows goes through L1 (warm within the launch); each weight slice is read
// ~once per step instead of once per batch row.
// Parities: h/c read buf[t&1], write buf[(t+1)&1]; ctx read buf[(t+1)&1] (= step t-1),
// zero buf[t&1] (accumulated by k_attn(t)).
__global__ void k_step(int t, const float* __restrict__ Wpg,
                       const float* __restrict__ bout, float* __restrict__ outp) {
    int p = blockIdx.x, tid = threadIdx.x;
    __shared__ float sred[256];
    __shared__ float sg[256];   // [rl=g*4+jl][b]
    const float* hb   = g_h   + (t & 1) * (BB * HH);
    const float* cb   = g_c   + (t & 1) * (BB * HH);
    const float* ctxb = g_ctx + ((t + 1) & 1) * (BB * 2 * HH);

    if (t > 0) {
        // ---- out(t-1)[b, j] = [h_new; ctx] . Wout[j,:] + bout[j], k-split by 4 ----
        {
            int kq = tid >> 6, r = tid & 63;
            int b = r >> 2, jl = r & 3;
            int j = p * 4 + jl;
            const float* hrow = hb + b * 256;
            const float* crow = ctxb + b * 512 - 256;   // index with k in [256,768)
            float acc = 0.f;
            int k0 = kq * 192;
#pragma unroll 4
            for (int k = k0; k < k0 + 192; k++) {
                float hv = (k < 256) ? hrow[k] : crow[k];
                acc += hv * g_WoutT[k * 256 + j];
            }
            sred[tid] = acc;
        }
        __syncthreads();
        if (tid < 64) {
            int b = tid >> 2, jl = tid & 3;
            float o = sred[tid] + sred[64 + tid] + sred[128 + tid] + sred[192 + tid]
                    + bout[p * 4 + jl];
            outp[OUT_OFF + (size_t)((t - 1) * BB + b) * 256 + p * 4 + jl] = o;
        }
        __syncthreads();
        // ---- p_gen(t-1): blocks p<16 each handle batch b=p ----
        if (p < 16) {
            // concat order [ctx(512), h(256), c(256), x(128:precomputed)] . Wpg
            float v0 = ctxb[p * 512 + tid]        * Wpg[tid];
            float v1 = ctxb[p * 512 + 256 + tid]  * Wpg[256 + tid];
            float v2 = hb[p * 256 + tid]          * Wpg[512 + tid];
            float v3 = cb[p * 256 + tid]          * Wpg[768 + tid];
            sred[tid] = (v0 + v1) + (v2 + v3);
            __syncthreads();
            for (int s = 128; s > 0; s >>= 1) {
                if (tid < s) sred[tid] += sred[tid + s];
                __syncthreads();
            }
            if (tid == 0)
                outp[PG_OFF + (t - 1) * BB + p] = sigf(sred[0] + g_px[(t - 1) * BB + p]);
            __syncthreads();
        }
    }

    // ---- gates: 16 rows (4 gates x 4 j) x 16 batch per block ----
    {
        int rl = tid >> 4, b = tid & 15;
        int g = rl >> 2, jl = rl & 3;
        int row = g * 256 + p * 4 + jl;
        float acc = g_Xg[(size_t)(t * BB + b) * 1024 + row];
        const float* hrow = hb + b * 256;
        const float* wp = g_WhhT + row;
        float a0 = 0, a1 = 0, a2 = 0, a3 = 0;
#pragma unroll 4
        for (int k = 0; k < 256; k += 4) {
            a0 += hrow[k]     * wp[(size_t)(k)     * 1024];
            a1 += hrow[k + 1] * wp[(size_t)(k + 1) * 1024];
            a2 += hrow[k + 2] * wp[(size_t)(k + 2) * 1024];
            a3 += hrow[k + 3] * wp[(size_t)(k + 3) * 1024];
        }
        sg[rl * 16 + b] = acc + (a0 + a1) + (a2 + a3);
    }
    __syncthreads();
    // ---- LSTM elementwise: 4 j x 16 b per block ----
    if (tid < 64) {
        int jl = tid >> 4, b = tid & 15;
        int j = p * 4 + jl;
        float ig = sg[(0 * 4 + jl) * 16 + b];
        float fg = sg[(1 * 4 + jl) * 16 + b];
        float gg = sg[(2 * 4 + jl) * 16 + b];
        float og = sg[(3 * 4 + jl) * 16 + b];
        float cn = sigf(fg) * cb[b * 256 + j] + sigf(ig) * tanh_fast(gg);
        float hn = sigf(og) * tanh_fast(cn);
        g_c[((t + 1) & 1) * (BB * HH) + b * 256 + j] = cn;
        g_h[((t + 1) & 1) * (BB * HH) + b * 256 + j] = hn;
    }
    // ---- zero ctx accumulator for this step (parity t&1) ----
    if (p < 16) {
        g_ctx[(t & 1) * (BB * 2 * HH) + p * 512 + tid] = 0.f;
        g_ctx[(t & 1) * (BB * 2 * HH) + p * 512 + 256 + tid] = 0.f;
    }
}

// dec_feat = [h_new; c_new] @ Ws^T + bs ; grid 64 (4-wide j slices) x 256, k-split 4
__global__ void k_dec(int t, const float* __restrict__ bs) {
    int p = blockIdx.x, tid = threadIdx.x;
    __shared__ float sred[256];
    const float* hb = g_h + ((t + 1) & 1) * (BB * HH);
    const float* cb = g_c + ((t + 1) & 1) * (BB * HH);
    int kq = tid >> 6, r = tid & 63;
    int b = r >> 2, jl = r & 3;
    int j = p * 4 + jl;
    const float* hrow = hb + b * 256;
    const float* crow = cb + b * 256 - 256;   // index with k in [256,512)
    float acc = 0.f;
    int k0 = kq * 128;
#pragma unroll 4
    for (int k = k0; k < k0 + 128; k++) {
        float v = (k < 256) ? hrow[k] : crow[k];
        acc += v * g_WsT[k * 256 + j];
    }
    sred[tid] = acc;
    __syncthreads();
    if (tid < 64) {
        int b2 = tid >> 2, jl2 = tid & 3;
        g_dec[b2 * 256 + p * 4 + jl2] =
            sred[tid] + sred[64 + tid] + sred[128 + tid] + sred[192 + tid] + bs[p * 4 + jl2];
    }
}

// e[b,l] = sum_h v[h] * tanh(enc_feat[b,l,h] + dec_feat[b,h]) ; grid (32,16) x 256
__global__ void k_e(const float* __restrict__ v_in) {
    int lc = blockIdx.x, b = blockIdx.y, tid = threadIdx.x;
    __shared__ float s_df[256], s_v[256];
    s_df[tid] = g_dec[b * 256 + tid];
    s_v[tid] = v_in[tid];
    __syncthreads();
    int w = tid >> 5, lane = tid & 31;
    int l0 = lc * 64 + w * 8;
#pragma unroll
    for (int i = 0; i < 8; i++) {
        int l = l0 + i;
        const float* ef = g_enc_feat + (size_t)(b * LL + l) * 256;
        float acc = 0.f;
#pragma unroll
        for (int m2 = 0; m2 < 8; m2++) {
            int h = m2 * 32 + lane;
            acc += s_v[h] * tanh_fast(ef[h] + s_df[h]);
        }
        for (int off = 16; off; off >>= 1) acc += __shfl_down_sync(0xffffffffu, acc, off);
        if (lane == 0) g_e[b * LL + l] = acc;
    }
}

// softmax(e)*mask / renorm (denominators cancel: a = exp(e-mx)*mask / sum(exp*mask)),
// write attn to d_out, accumulate ctx (fp16 encoder replica) via atomics.
// grid (8,16) x 256. Each block: redundant softmax reduction, then its 256-l chunk.
__global__ void k_attn(int t, const float* __restrict__ mask, float* __restrict__ outp) {
    int cc = blockIdx.x, b = blockIdx.y, tid = threadIdx.x;
    __shared__ float s_e[2048], s_a[256], s_red[256];
    const float* eb = g_e + b * LL;
    const float* mb = mask + b * LL;
    float lmax = -1e30f;
    for (int i = tid; i < 2048; i += 256) {
        float val = eb[i];
        s_e[i] = val;
        lmax = fmaxf(lmax, val);
    }
    s_red[tid] = lmax;
    __syncthreads();
    for (int s = 128; s > 0; s >>= 1) {
        if (tid < s) s_red[tid] = fmaxf(s_red[tid], s_red[tid + s]);
        __syncthreads();
    }
    float mx = s_red[0];
    __syncthreads();
    float lsum = 0.f;
    for (int i = tid; i < 2048; i += 256) lsum += __expf(s_e[i] - mx) * mb[i];
    s_red[tid] = lsum;
    __syncthreads();
    for (int s = 128; s > 0; s >>= 1) {
        if (tid < s) s_red[tid] += s_red[tid + s];
        __syncthreads();
    }
    float inv = __fdividef(1.f, s_red[0]);
    int l = cc * 256 + tid;
    float a = __expf(s_e[l] - mx) * mb[l] * inv;
    outp[ATTN_OFF + (size_t)(t * BB + b) * LL + l] = a;
    s_a[tid] = a;
    __syncthreads();
    // ctx partial over this 256-l chunk from the fp16 replica.
    // thread owns half2 column tid (fp32 columns 2*tid, 2*tid+1).
    float acc0 = 0.f, acc1 = 0.f;
    const __half2* es = g_enc16 + (size_t)(b * LL + cc * 256) * 256;
#pragma unroll 4
    for (int i = 0; i < 256; i++) {
        float av = s_a[i];
        float2 f = __half22float2(es[(size_t)i * 256 + tid]);
        acc0 += av * f.x;
        acc1 += av * f.y;
    }
    float* ctx = g_ctx + (t & 1) * (BB * 2 * HH) + b * 512;
    atomicAdd(&ctx[2 * tid], acc0);
    atomicAdd(&ctx[2 * tid + 1], acc1);
}

__global__ void k_copyhc(float* __restrict__ outp) {
    int i = blockIdx.x * 256 + threadIdx.x;   // 4096 (final h/c live in parity-0 buffers)
    outp[HF_OFF + i] = g_h[i];
    outp[CF_OFF + i] = g_c[i];
}

// ---------------- launcher ----------------
extern "C" void kernel_launch(void* const* d_in, const int* in_sizes, int n_in,
                              void* d_out, int out_size) {
    const float* dec_in = (const float*)d_in[0];
    const float* h0     = (const float*)d_in[1];
    const float* c0     = (const float*)d_in[2];
    const float* enc_st = (const float*)d_in[3];
    const float* emask  = (const float*)d_in[4];
    const float* Wh     = (const float*)d_in[5];
    const float* bh     = (const float*)d_in[6];
    const float* Ws     = (const float*)d_in[7];
    const float* bs     = (const float*)d_in[8];
    const float* v      = (const float*)d_in[9];
    const float* Wx     = (const float*)d_in[10];
    const float* bx     = (const float*)d_in[11];
    const float* Wih    = (const float*)d_in[12];
    const float* bih    = (const float*)d_in[13];
    const float* Whh    = (const float*)d_in[14];
    const float* bhh    = (const float*)d_in[15];
    const float* Wpg    = (const float*)d_in[16];
    const float* bpg    = (const float*)d_in[17];
    const float* Wout   = (const float*)d_in[18];
    const float* bout   = (const float*)d_in[19];
    float* outp = (float*)d_out;

    // precompute
    k_init<<<16, 256>>>(h0, c0);
    k_transpose<<<512, 256>>>(Whh, Ws, Wout, Wih);
    k_enc16<<<BB * LL * HH / 256, 256>>>(enc_st);
    k_encfeat<<<dim3(512, 4), 256>>>(enc_st, Wh, bh);
    k_X<<<T_STEPS * BB, 128>>>(dec_in, Wx, bx);
    k_Xg<<<T_STEPS * BB / 8, 256>>>(bih, bhh);
    k_px<<<(T_STEPS * BB + 127) / 128, 128>>>(Wpg, bpg);

    // recurrent loop; t == T_STEPS does only the final out(99)/p_gen(99) epilogue
    // (its gates phase reads the zero-padded tail of g_Xg and writes dead parity-1 state)
    for (int t = 0; t <= T_STEPS; t++) {
        k_step<<<64, 256>>>(t, Wpg, bout, outp);
        if (t < T_STEPS) {
            k_dec<<<64, 256>>>(t, bs);
            k_e<<<dim3(32, BB), 256>>>(v);
            k_attn<<<dim3(8, BB), 256>>>(t, emask, outp);
        }
    }
    k_copyhc<<<16, 256>>>(outp);
}

// round 10
// speedup vs baseline: 1.1838x; 1.1838x over previous
#include <cuda_runtime.h>
#include <cuda_fp16.h>
#include <cstddef>

// ---------------- problem constants ----------------
#define T_STEPS 100
#define BB 16
#define EE 128
#define HH 256
#define LL 2048
#define NBLK 148
// output layout (flattened tuple: outputs, h_f, c_f, attn, p_gens)
#define OUT_OFF  0                    // [100,16,256]
#define HF_OFF   409600               // [16,256]
#define CF_OFF   413696               // [16,256]
#define ATTN_OFF 417792               // [100,16,2048]
#define PG_OFF   3694592              // [100,16,1]

// ---------------- device scratch ----------------
__device__ float   g_encE[BB * LL * HH];              // E = exp(2*enc_feat), fp32
__device__ __half2 g_enc16[BB * LL * HH];             // fp16 encoder replica (ctx path)
__device__ float g_X [T_STEPS * BB * EE];
__device__ float g_Xg[T_STEPS * BB * 4 * HH];         // x@Wih^T+bih+bhh
__device__ float g_px[T_STEPS * BB];
__device__ float g_h[2 * BB * HH];                    // double-buffered by parity
__device__ float g_c[2 * BB * HH];
__device__ float g_dec[BB * HH];                      // D = exp(2*dec_feat)
__device__ float g_e[BB * LL];
__device__ float g_ctx[2 * BB * 2 * HH];
__device__ float g_WhhT[HH * 4 * HH];                 // [256][1024] k-major
__device__ float g_WsT [2 * HH * HH];                 // [512][256]
__device__ float g_WoutT[3 * HH * HH];                // [768][256]
__device__ float g_WihT[EE * 4 * HH];                 // [128][1024]
__device__ unsigned g_bar_count;                      // zero-init; returns to 0 each call
__device__ unsigned g_bar_gen;                        // monotonic across replays

// ---------------- helpers ----------------
__device__ __forceinline__ float sigf(float x) {
    return __fdividef(1.f, 1.f + __expf(-x));
}
__device__ __forceinline__ float tanh_fast(float x) {
    float ax = fabsf(x);
    float t = __expf(-2.f * ax);
    float r = (1.f - t) * __fdividef(1.f, 1.f + t);
    return copysignf(r, x);
}

// grid-wide barrier.
// Release: EVERY thread fences (publishes its own prior stores device-wide),
// then one arrival per block. Acquire: L2 (cg) spin on the generation word.
// All cross-phase data is read via __ldcg, so L1 staleness cannot bite.
__device__ __forceinline__ void gbar() {
    __threadfence();
    __syncthreads();
    if (threadIdx.x == 0) {
        unsigned gen;
        asm volatile("ld.global.cg.u32 %0, [%1];" : "=r"(gen) : "l"(&g_bar_gen) : "memory");
        unsigned t = atomicAdd(&g_bar_count, 1u);
        if (t == gridDim.x - 1u) {
            atomicExch(&g_bar_count, 0u);
            __threadfence();
            atomicExch(&g_bar_gen, gen + 1u);
        } else {
            unsigned cur;
            do {
                __nanosleep(32);
                asm volatile("ld.global.cg.u32 %0, [%1];" : "=r"(cur) : "l"(&g_bar_gen) : "memory");
            } while (cur == gen);
        }
    }
    __syncthreads();
}

// ---------------- precompute kernels ----------------
// launch #1: weight transposes + h/c init
__global__ void k_transpose(const float* __restrict__ Whh, const float* __restrict__ Ws,
                            const float* __restrict__ Wout, const float* __restrict__ Wih,
                            const float* __restrict__ h0, const float* __restrict__ c0) {
    int stride = gridDim.x * blockDim.x;
    int tid = blockIdx.x * blockDim.x + threadIdx.x;
    for (int i = tid; i < BB * HH; i += stride) { g_h[i] = h0[i]; g_c[i] = c0[i]; }
    for (int i = tid; i < 1024 * 256; i += stride) {
        int j = i / 256, k = i % 256;
        g_WhhT[k * 1024 + j] = Whh[i];
    }
    for (int i = tid; i < 256 * 512; i += stride) {
        int j = i / 512, k = i % 512;
        g_WsT[k * 256 + j] = Ws[i];
    }
    for (int i = tid; i < 256 * 768; i += stride) {
        int j = i / 768, k = i % 768;
        g_WoutT[k * 256 + j] = Wout[i];
    }
    for (int i = tid; i < 1024 * 128; i += stride) {
        int j = i / 128, k = i % 128;
        g_WihT[k * 1024 + j] = Wih[i];
    }
}

// launch #2: fp16 replica of encoder_states
__global__ void k_enc16(const float* __restrict__ es) {
    int i = blockIdx.x * 256 + threadIdx.x;
    float2 f = ((const float2*)es)[i];
    g_enc16[i] = __floats2half2_rn(f.x, f.y);
}

// launch #3: E = exp(2*(encoder_states @ Wh^T + bh)) ; 64x64 tile, 4x4/thread
// (tanh(a+b) = 1 - 2/(e^{2a} e^{2b} + 1): e^{2a} precomputed here once.)
__global__ void k_encfeat(const float* __restrict__ A, const float* __restrict__ Wh,
                          const float* __restrict__ bh) {
    __shared__ __align__(16) float As[16 * 64];
    __shared__ __align__(16) float Bs[16 * 64];
    int m0 = blockIdx.x * 64, n0 = blockIdx.y * 64;
    int tid = threadIdx.x;
    int r = tid >> 2, c4 = (tid & 3) << 2;
    int rm = (tid & 15) << 2, rn = (tid >> 4) << 2;
    float acc[4][4] = {};
    for (int k0 = 0; k0 < 512; k0 += 16) {
        float4 av = *(const float4*)(A + (size_t)(m0 + r) * 512 + k0 + c4);
        As[(c4 + 0) * 64 + r] = av.x; As[(c4 + 1) * 64 + r] = av.y;
        As[(c4 + 2) * 64 + r] = av.z; As[(c4 + 3) * 64 + r] = av.w;
        float4 bv = *(const float4*)(Wh + (size_t)(n0 + r) * 512 + k0 + c4);
        Bs[(c4 + 0) * 64 + r] = bv.x; Bs[(c4 + 1) * 64 + r] = bv.y;
        Bs[(c4 + 2) * 64 + r] = bv.z; Bs[(c4 + 3) * 64 + r] = bv.w;
        __syncthreads();
#pragma unroll
        for (int kk = 0; kk < 16; kk++) {
            float4 a  = *(const float4*)(As + kk * 64 + rm);
            float4 bb = *(const float4*)(Bs + kk * 64 + rn);
            acc[0][0] += a.x * bb.x; acc[0][1] += a.x * bb.y; acc[0][2] += a.x * bb.z; acc[0][3] += a.x * bb.w;
            acc[1][0] += a.y * bb.x; acc[1][1] += a.y * bb.y; acc[1][2] += a.y * bb.z; acc[1][3] += a.y * bb.w;
            acc[2][0] += a.z * bb.x; acc[2][1] += a.z * bb.y; acc[2][2] += a.z * bb.z; acc[2][3] += a.z * bb.w;
            acc[3][0] += a.w * bb.x; acc[3][1] += a.w * bb.y; acc[3][2] += a.w * bb.z; acc[3][3] += a.w * bb.w;
        }
        __syncthreads();
    }
#pragma unroll
    for (int i = 0; i < 4; i++)
#pragma unroll
        for (int j = 0; j < 4; j++)
            g_encE[(size_t)(m0 + rm + i) * 256 + n0 + rn + j] =
                __expf(2.f * (acc[i][j] + bh[n0 + rn + j]));
}

// launch #4: X[m,:] = inp[m,:128] @ WxE^T + bx, plus px[m] (pointer-gen x-part)
__global__ void k_X(const float* __restrict__ inp, const float* __restrict__ Wx,
                    const float* __restrict__ bx, const float* __restrict__ Wpg,
                    const float* __restrict__ bpg) {
    int m = blockIdx.x, tid = threadIdx.x;   // 128 threads
    __shared__ float s_in[128], s_r[128];
    s_in[tid] = inp[m * 128 + tid];
    __syncthreads();
    const float* w = Wx + (size_t)tid * 640;
    float a0 = 0, a1 = 0, a2 = 0, a3 = 0;
#pragma unroll 8
    for (int k = 0; k < 128; k += 4) {
        a0 += s_in[k] * w[k]; a1 += s_in[k + 1] * w[k + 1];
        a2 += s_in[k + 2] * w[k + 2]; a3 += s_in[k + 3] * w[k + 3];
    }
    float xv = bx[tid] + (a0 + a1) + (a2 + a3);
    g_X[m * 128 + tid] = xv;
    s_r[tid] = xv * Wpg[1024 + tid];
    __syncthreads();
    for (int s = 64; s > 0; s >>= 1) {
        if (tid < s) s_r[tid] += s_r[tid + s];
        __syncthreads();
    }
    if (tid == 0) g_px[m] = s_r[0] + bpg[0];
}

// launch #5: Xg[m,:] = X[m,:] @ Wih^T + bih + bhh ; 8 rows/block
__global__ void k_Xg(const float* __restrict__ bih, const float* __restrict__ bhh) {
    int m0 = blockIdx.x * 8;
    int tid = threadIdx.x;     // 256
    __shared__ float sx[8 * 128];
#pragma unroll
    for (int i = 0; i < 4; i++) sx[tid + i * 256] = g_X[m0 * 128 + tid + i * 256];
    __syncthreads();
#pragma unroll
    for (int g = 0; g < 4; g++) {
        int row = g * 256 + tid;
        float base = bih[row] + bhh[row];
        float acc[8];
#pragma unroll
        for (int mm = 0; mm < 8; mm++) acc[mm] = base;
        for (int k = 0; k < 128; k++) {
            float w = g_WihT[k * 1024 + row];
#pragma unroll
            for (int mm = 0; mm < 8; mm++) acc[mm] += sx[mm * 128 + k] * w;
        }
#pragma unroll
        for (int mm = 0; mm < 8; mm++) g_Xg[(m0 + mm) * 1024 + row] = acc[mm];
    }
}

// ---------------- launch #6: persistent recurrent loop ----------------
// 148 blocks x 256 threads, all wave-1 resident (grid <= SM count, 1 CTA/SM).
// Per step: A) gates+LSTM | out(t-1) | p_gen(t-1) | ctx-zero   (all 148 blocks busy)
//           B) D=exp(2*dec_feat)   C) energies e via exp-trick   D) softmax + ctx
// Parities: h/c read buf[t&1] write buf[(t+1)&1]; ctx read buf[(t+1)&1], accumulate buf[t&1].
__global__ void __launch_bounds__(256, 1)
k_loop(const float* __restrict__ Wpg, const float* __restrict__ bout,
       const float* __restrict__ bs, const float* __restrict__ v_in,
       const float* __restrict__ mask, float* __restrict__ outp) {
    const int bx = blockIdx.x;
    const int tid = threadIdx.x;
    __shared__ __align__(16) float s_buf[4352];  // h-stage(16*257)/epi stage/s_e(2048)
    __shared__ __align__(16) float s_red[256];
    __shared__ __align__(16) float s_a[256];
    __shared__ __align__(16) float s_df[256];
    __shared__ __align__(16) float s_v[256];

    s_v[tid] = v_in[tid];
    // Vsum = sum_h v[h] (for e = Vsum - 2*sum v*rcp(E*D+1))
    s_red[tid] = s_v[tid];
    __syncthreads();
    for (int s = 128; s > 0; s >>= 1) {
        if (tid < s) s_red[tid] += s_red[tid + s];
        __syncthreads();
    }
    const float Vsum = s_red[0];
    __syncthreads();

    for (int t = 0; t <= T_STEPS; t++) {
        const float* hb   = g_h   + (t & 1) * (BB * HH);
        const float* cb   = g_c   + (t & 1) * (BB * HH);
        const float* ctxb = g_ctx + ((t + 1) & 1) * (BB * 2 * HH);

        // ===================== PHASE A =====================
        if (bx < 64) {
            if (t < T_STEPS) {
                // gates + LSTM for j-slice p=bx (4 j), all 16 b; h staged conflict-free
                int p = bx;
                for (int i = tid; i < 4096; i += 256)
                    s_buf[(i >> 8) * 257 + (i & 255)] = __ldcg(hb + i);
                __syncthreads();
                int rl = tid >> 4, b = tid & 15;
                int g = rl >> 2, jl = rl & 3;
                int row = g * 256 + p * 4 + jl;
                float acc = g_Xg[(size_t)(t * BB + b) * 1024 + row];
                const float* hs = s_buf + b * 257;
                const float* wp = g_WhhT + row;
                float a0 = 0, a1 = 0, a2 = 0, a3 = 0;
#pragma unroll 4
                for (int k = 0; k < 256; k += 4) {
                    a0 += hs[k]     * wp[(size_t)(k)     * 1024];
                    a1 += hs[k + 1] * wp[(size_t)(k + 1) * 1024];
                    a2 += hs[k + 2] * wp[(size_t)(k + 2) * 1024];
                    a3 += hs[k + 3] * wp[(size_t)(k + 3) * 1024];
                }
                acc += (a0 + a1) + (a2 + a3);
                s_red[rl * 16 + b] = acc;
                __syncthreads();
                if (tid < 64) {
                    int jl2 = tid >> 4, b2 = tid & 15;
                    int j = p * 4 + jl2;
                    float ig = s_red[(0 * 4 + jl2) * 16 + b2];
                    float fg = s_red[(1 * 4 + jl2) * 16 + b2];
                    float gg = s_red[(2 * 4 + jl2) * 16 + b2];
                    float og = s_red[(3 * 4 + jl2) * 16 + b2];
                    float cv = __ldcg(cb + b2 * 256 + j);
                    float cn = sigf(fg) * cv + sigf(ig) * tanh_fast(gg);
                    float hn = sigf(og) * tanh_fast(cn);
                    g_c[((t + 1) & 1) * (BB * HH) + b2 * 256 + j] = cn;
                    g_h[((t + 1) & 1) * (BB * HH) + b2 * 256 + j] = hn;
                }
            } else if (bx < 16) {
                // final h/c copy (parity 0 after t=99 write)
                int i = bx * 256 + tid;
                outp[HF_OFF + i] = __ldcg(&g_h[i]);
                outp[CF_OFF + i] = __ldcg(&g_c[i]);
            }
        } else if (bx < 128) {
            if (t > 0) {
                // out(t-1)[b0, jq*64..+64] = [h;ctx].Wout + bout, k-split x4
                int b0 = (bx - 64) >> 2, jq = (bx - 64) & 3;
                for (int i = tid; i < 768; i += 256)
                    s_buf[i] = (i < 256) ? __ldcg(hb + b0 * 256 + i)
                                         : __ldcg(ctxb + b0 * 512 + (i - 256));
                __syncthreads();
                int kq = tid >> 6, jt = tid & 63;
                int j = jq * 64 + jt;
                float acc = 0.f;
                int k0 = kq * 192;
#pragma unroll 4
                for (int k = k0; k < k0 + 192; k++)
                    acc += s_buf[k] * g_WoutT[k * 256 + j];
                s_buf[1024 + tid] = acc;
                __syncthreads();
                if (tid < 64) {
                    float o = s_buf[1024 + tid] + s_buf[1088 + tid]
                            + s_buf[1152 + tid] + s_buf[1216 + tid] + bout[jq * 64 + tid];
                    outp[OUT_OFF + (size_t)((t - 1) * BB + b0) * 256 + jq * 64 + tid] = o;
                }
            }
        } else if (bx < 144) {
            if (t > 0) {
                // p_gen(t-1), concat order [ctx, h, c, x(precomputed)]
                int b = bx - 128;
                float v0 = __ldcg(ctxb + b * 512 + tid)       * Wpg[tid];
                float v1 = __ldcg(ctxb + b * 512 + 256 + tid) * Wpg[256 + tid];
                float v2 = __ldcg(hb + b * 256 + tid)         * Wpg[512 + tid];
                float v3 = __ldcg(cb + b * 256 + tid)         * Wpg[768 + tid];
                s_red[tid] = (v0 + v1) + (v2 + v3);
                __syncthreads();
                for (int s = 128; s > 0; s >>= 1) {
                    if (tid < s) s_red[tid] += s_red[tid + s];
                    __syncthreads();
                }
                if (tid == 0)
                    outp[PG_OFF + (t - 1) * BB + b] = sigf(s_red[0] + g_px[(t - 1) * BB + b]);
            }
        } else {
            if (t < T_STEPS) {
                // zero ctx accumulator parity t&1
                float* cz = g_ctx + (t & 1) * (BB * 2 * HH) + (bx - 144) * 2048;
                for (int i = tid; i < 2048; i += 256) cz[i] = 0.f;
            }
        }

        if (t == T_STEPS) break;
        gbar();

        // ===================== PHASE B: D = exp(2*dec_feat) =====================
        if (bx < 64) {
            int b0 = bx >> 2, jq = bx & 3;
            const float* hn = g_h + ((t + 1) & 1) * (BB * HH);
            const float* cn = g_c + ((t + 1) & 1) * (BB * HH);
            for (int i = tid; i < 512; i += 256)
                s_buf[i] = (i < 256) ? __ldcg(hn + b0 * 256 + i)
                                     : __ldcg(cn + b0 * 256 + (i - 256));
            __syncthreads();
            int kq = tid >> 6, jt = tid & 63;
            int j = jq * 64 + jt;
            float acc = 0.f;
            int k0 = kq * 128;
#pragma unroll 4
            for (int k = k0; k < k0 + 128; k++)
                acc += s_buf[k] * g_WsT[k * 256 + j];
            s_buf[1024 + tid] = acc;
            __syncthreads();
            if (tid < 64) {
                float df = s_buf[1024 + tid] + s_buf[1088 + tid] + s_buf[1152 + tid]
                         + s_buf[1216 + tid] + bs[jq * 64 + tid];
                g_dec[b0 * 256 + jq * 64 + tid] = __expf(2.f * df);
            }
        }
        gbar();

        // ===================== PHASE C: energies e (exp-trick) =====================
        // e[b,l] = Vsum - 2 * sum_h v[h] / (E[b,l,h]*D[b,h] + 1)
        // 1024 tasks of 32 l each (balance <2%); per task 4 l per warp.
        for (int task = bx; task < 1024; task += NBLK) {
            int lc = task >> 4, b = task & 15;
            __syncthreads();
            s_df[tid] = __ldcg(g_dec + b * 256 + tid);
            __syncthreads();
            int w = tid >> 5, lane = tid & 31;
            int l0 = lc * 32 + w * 4;
            const float4* sv4 = (const float4*)s_v;
            const float4* sd4 = (const float4*)s_df;
#pragma unroll
            for (int i = 0; i < 4; i++) {
                int l = l0 + i;
                const float4* ef4 = (const float4*)(g_encE + (size_t)(b * LL + l) * 256);
                float acc = 0.f;
#pragma unroll
                for (int m2 = 0; m2 < 2; m2++) {
                    int j = m2 * 32 + lane;
                    float4 E = ef4[j];
                    float4 D = sd4[j];
                    float4 V = sv4[j];
                    acc = fmaf(V.x, __fdividef(1.f, fmaf(E.x, D.x, 1.f)), acc);
                    acc = fmaf(V.y, __fdividef(1.f, fmaf(E.y, D.y, 1.f)), acc);
                    acc = fmaf(V.z, __fdividef(1.f, fmaf(E.z, D.z, 1.f)), acc);
                    acc = fmaf(V.w, __fdividef(1.f, fmaf(E.w, D.w, 1.f)), acc);
                }
                for (int off = 16; off; off >>= 1)
                    acc += __shfl_down_sync(0xffffffffu, acc, off);
                if (lane == 0) g_e[b * LL + l] = Vsum - 2.f * acc;
            }
        }
        gbar();

        // ===================== PHASE D: softmax + attn out + ctx =====================
        if (bx < 128) {
            int b = bx >> 3, cc = bx & 7;
            const float* mb = mask + b * LL;
            float lmax = -1e30f;
            for (int i = tid; i < 2048; i += 256) {
                float val = __ldcg(g_e + b * LL + i);
                s_buf[i] = val;
                lmax = fmaxf(lmax, val);
            }
            s_red[tid] = lmax;
            __syncthreads();
            for (int s = 128; s > 0; s >>= 1) {
                if (tid < s) s_red[tid] = fmaxf(s_red[tid], s_red[tid + s]);
                __syncthreads();
            }
            float mx = s_red[0];
            __syncthreads();
            float lsum = 0.f;
            for (int i = tid; i < 2048; i += 256) lsum += __expf(s_buf[i] - mx) * mb[i];
            s_red[tid] = lsum;
            __syncthreads();
            for (int s = 128; s > 0; s >>= 1) {
                if (tid < s) s_red[tid] += s_red[tid + s];
                __syncthreads();
            }
            float inv = __fdividef(1.f, s_red[0]);
            int l = cc * 256 + tid;
            float a = __expf(s_buf[l] - mx) * mb[l] * inv;
            outp[ATTN_OFF + (size_t)(t * BB + b) * LL + l] = a;
            s_a[tid] = a;
            __syncthreads();
            float acc0 = 0.f, acc1 = 0.f;
            const __half2* es = g_enc16 + (size_t)(b * LL + cc * 256) * 256;
#pragma unroll 4
            for (int i = 0; i < 256; i++) {
                float av = s_a[i];
                float2 f = __half22float2(es[(size_t)i * 256 + tid]);
                acc0 += av * f.x;
                acc1 += av * f.y;
            }
            float* ctx = g_ctx + (t & 1) * (BB * 2 * HH) + b * 512;
            atomicAdd(&ctx[2 * tid], acc0);
            atomicAdd(&ctx[2 * tid + 1], acc1);
        }
        gbar();
    }
}

// ---------------- launcher ----------------
extern "C" void kernel_launch(void* const* d_in, const int* in_sizes, int n_in,
                              void* d_out, int out_size) {
    const float* dec_in = (const float*)d_in[0];
    const float* h0     = (const float*)d_in[1];
    const float* c0     = (const float*)d_in[2];
    const float* enc_st = (const float*)d_in[3];
    const float* emask  = (const float*)d_in[4];
    const float* Wh     = (const float*)d_in[5];
    const float* bh     = (const float*)d_in[6];
    const float* Ws     = (const float*)d_in[7];
    const float* bs     = (const float*)d_in[8];
    const float* v      = (const float*)d_in[9];
    const float* Wx     = (const float*)d_in[10];
    const float* bx     = (const float*)d_in[11];
    const float* Wih    = (const float*)d_in[12];
    const float* bih    = (const float*)d_in[13];
    const float* Whh    = (const float*)d_in[14];
    const float* bhh    = (const float*)d_in[15];
    const float* Wpg    = (const float*)d_in[16];
    const float* bpg    = (const float*)d_in[17];
    const float* Wout   = (const float*)d_in[18];
    const float* bout   = (const float*)d_in[19];
    float* outp = (float*)d_out;

    k_transpose<<<512, 256>>>(Whh, Ws, Wout, Wih, h0, c0);          // #1
    k_enc16<<<BB * LL * HH / 256, 256>>>(enc_st);                    // #2
    k_encfeat<<<dim3(512, 4), 256>>>(enc_st, Wh, bh);                // #3
    k_X<<<T_STEPS * BB, 128>>>(dec_in, Wx, bx, Wpg, bpg);            // #4
    k_Xg<<<T_STEPS * BB / 8, 256>>>(bih, bhh);                       // #5
    k_loop<<<NBLK, 256>>>(Wpg, bout, bs, v, emask, outp);            // #6 (ncu -s 5 target)
}